// round 10
// baseline (speedup 1.0000x reference)
#include <cuda_runtime.h>
#include <cuda_bf16.h>
#include <cstdint>
#include <cfloat>

// ---------------------------------------------------------------------------
// GATv2 3-layer forward.  CSR + online-softmax fused edges + bf16 MMA GEMM.
// Layer-3 node transform fused into layer-2 edge kernel epilogue.
// N=50000, E=500000 (+N self loops), F_IN=128, HID=384 (8 heads x 48), OUT=2.
// ---------------------------------------------------------------------------

#define NN_MAX 50000
#define EE_MAX 500000
#define ET_MAX (EE_MAX + NN_MAX)
#define HID 384
#define NHEAD 8
#define CH 48
#define NEG 0.2f

// ------------------------- scratch (device globals) ------------------------
__device__ float g_xl[NN_MAX * HID];
__device__ float g_xr[NN_MAX * HID];
__device__ float g_feat[NN_MAX * HID];
__device__ int   g_deg[NN_MAX];
__device__ int   g_rowptr[NN_MAX + 1];
__device__ int   g_pos[NN_MAX];
__device__ int   g_eperm[ET_MAX];
__device__ int   g_bsum[256];
__device__ float g_xl3[NN_MAX * 2];
__device__ float g_xr3[NN_MAX * 2];

// ------------------------------ CSR build -----------------------------------
__global__ void deg_init_kernel(int* deg, int nN) {
    int i = blockIdx.x * blockDim.x + threadIdx.x;
    if (i < nN) deg[i] = 1;
}

__global__ void deg_hist_kernel(const int* __restrict__ dst, int* deg, int E) {
    int e = blockIdx.x * blockDim.x + threadIdx.x;
    if (e < E) atomicAdd(&deg[dst[e]], 1);
}

__global__ void scan_block_sums(const int* __restrict__ deg, int* bsum, int nN) {
    __shared__ int sm[256];
    int i = blockIdx.x * 256 + threadIdx.x;
    sm[threadIdx.x] = (i < nN) ? deg[i] : 0;
    __syncthreads();
    for (int o = 128; o; o >>= 1) {
        if (threadIdx.x < o) sm[threadIdx.x] += sm[threadIdx.x + o];
        __syncthreads();
    }
    if (threadIdx.x == 0) bsum[blockIdx.x] = sm[0];
}

__global__ void scan_bsum_kernel(int* bsum, int nb) {
    __shared__ int sm[256];
    int t = threadIdx.x;
    int v = (t < nb) ? bsum[t] : 0;
    sm[t] = v;
    __syncthreads();
    for (int o = 1; o < 256; o <<= 1) {
        int add = (t >= o) ? sm[t - o] : 0;
        __syncthreads();
        sm[t] += add;
        __syncthreads();
    }
    if (t < nb) bsum[t] = sm[t] - v;
}

__global__ void scan_final_kernel(const int* __restrict__ deg, const int* __restrict__ bsum,
                                  int* rowptr, int* pos, int nN, int nEt) {
    __shared__ int sm[256];
    int t = threadIdx.x;
    int i = blockIdx.x * 256 + t;
    int v = (i < nN) ? deg[i] : 0;
    sm[t] = v;
    __syncthreads();
    for (int o = 1; o < 256; o <<= 1) {
        int add = (t >= o) ? sm[t - o] : 0;
        __syncthreads();
        sm[t] += add;
        __syncthreads();
    }
    if (i < nN) {
        int ex = sm[t] - v + bsum[blockIdx.x];
        rowptr[i] = ex;
        pos[i] = ex;
    }
    if (i == 0) rowptr[nN] = nEt;
}

__global__ void scatter_kernel(const int* __restrict__ src, const int* __restrict__ dst,
                               int* pos, int* eperm, int E, int nN) {
    int t = blockIdx.x * blockDim.x + threadIdx.x;
    if (t >= E + nN) return;
    int s, d;
    if (t < E) { s = src[t]; d = dst[t]; } else { s = d = t - E; }
    int p = atomicAdd(&pos[d], 1);
    eperm[p] = s;
}

// ---------------------------- MMA helpers -----------------------------------
static __device__ __forceinline__ uint32_t packbf(float x, float y) {
    __nv_bfloat162 h = __floats2bfloat162_rn(x, y);
    return *reinterpret_cast<uint32_t*>(&h);
}
static __device__ __forceinline__ void mma_bf16(float c[4], uint32_t a0, uint32_t a1,
                                                uint32_t a2, uint32_t a3,
                                                uint32_t b0, uint32_t b1) {
    asm volatile(
        "mma.sync.aligned.m16n8k16.row.col.f32.bf16.bf16.f32 "
        "{%0,%1,%2,%3}, {%4,%5,%6,%7}, {%8,%9}, {%0,%1,%2,%3};\n"
        : "+f"(c[0]), "+f"(c[1]), "+f"(c[2]), "+f"(c[3])
        : "r"(a0), "r"(a1), "r"(a2), "r"(a3), "r"(b0), "r"(b1));
}
static __device__ __forceinline__ void cpasync16(uint32_t dst, const void* src, int sz) {
    asm volatile("cp.async.cg.shared.global [%0], [%1], 16, %2;\n"
                 :: "r"(dst), "l"(src), "r"(sz));
}
static __device__ __forceinline__ void cpcommit() {
    asm volatile("cp.async.commit_group;\n");
}
template <int N>
static __device__ __forceinline__ void cpwait() {
    asm volatile("cp.async.wait_group %0;\n" :: "n"(N));
}

// -------------------- dual GEMM (xl and xr in one launch) --------------------
// C_half[M,Nc] = A[M,K] @ B_half[K,Nc] + bias_half.
// BM=128 BN=128 BK=16, 256 threads, warp tile 64x32, mma m16n8k16 bf16
// (fp32 smem, fragments packed to bf16 at register load).
__global__ __launch_bounds__(256, 2) void gemm_dual_bf16_kernel(
    const float* __restrict__ A,
    const float* __restrict__ Bl, const float* __restrict__ Br,
    const float* __restrict__ bl, const float* __restrict__ br,
    float* __restrict__ Cl, float* __restrict__ Cr,
    int M, int K, int Nc) {
    __shared__ float As[2][128][20];
    __shared__ float Bs[2][16][136];

    const int tid = threadIdx.x;
    const int lane = tid & 31;
    const int warpId = tid >> 5;
    const int warpM = warpId & 1;
    const int warpN = warpId >> 1;
    const int r = lane >> 2;
    const int c = lane & 3;

    const int nb = Nc >> 7;
    const int half = blockIdx.x / nb;
    const int colLocal = (blockIdx.x - half * nb) * 128;
    const int rowBase = blockIdx.y * 128;
    const float* B = half ? Br : Bl;
    const float* bias = half ? br : bl;
    float* C = half ? Cr : Cl;

    float acc[4][4][4];
#pragma unroll
    for (int i = 0; i < 4; i++)
#pragma unroll
        for (int j = 0; j < 4; j++)
#pragma unroll
            for (int k = 0; k < 4; k++) acc[i][j][k] = 0.f;

    int arow[2], akq[2], bk[2], bnq[2];
#pragma unroll
    for (int j = 0; j < 2; j++) {
        int s = tid * 2 + j;
        arow[j] = s >> 2;  akq[j] = (s & 3) << 2;
        bk[j] = s >> 5;    bnq[j] = (s & 31) << 2;
    }

    const int T = K >> 4;

    auto issue_tile = [&](int t, int s) {
#pragma unroll
        for (int j = 0; j < 2; j++) {
            int gr = rowBase + arow[j];
            int grc = gr < M ? gr : (M - 1);
            const float* gp = A + (size_t)grc * K + t * 16 + akq[j];
            uint32_t sa = (uint32_t)__cvta_generic_to_shared(&As[s][arow[j]][akq[j]]);
            cpasync16(sa, gp, gr < M ? 16 : 0);
        }
#pragma unroll
        for (int j = 0; j < 2; j++) {
            const float* gp = B + (size_t)(t * 16 + bk[j]) * Nc + colLocal + bnq[j];
            uint32_t sa = (uint32_t)__cvta_generic_to_shared(&Bs[s][bk[j]][bnq[j]]);
            cpasync16(sa, gp, 16);
        }
        cpcommit();
    };

    issue_tile(0, 0);

    for (int t = 0; t < T; t++) {
        int s = t & 1;
        if (t + 1 < T) {
            issue_tile(t + 1, s ^ 1);
            cpwait<1>();
        } else {
            cpwait<0>();
        }
        __syncthreads();

        // one m16n8k16 step covers the whole 16-deep tile
        uint32_t Ah[4][4], Bh[4][2];
#pragma unroll
        for (int mt = 0; mt < 4; mt++) {
            int m = warpM * 64 + mt * 16 + r;
            float2 a01 = *(const float2*)&As[s][m][2 * c];
            float2 a23 = *(const float2*)&As[s][m + 8][2 * c];
            float2 a45 = *(const float2*)&As[s][m][2 * c + 8];
            float2 a67 = *(const float2*)&As[s][m + 8][2 * c + 8];
            Ah[mt][0] = packbf(a01.x, a01.y);
            Ah[mt][1] = packbf(a23.x, a23.y);
            Ah[mt][2] = packbf(a45.x, a45.y);
            Ah[mt][3] = packbf(a67.x, a67.y);
        }
#pragma unroll
        for (int nt = 0; nt < 4; nt++) {
            int n = warpN * 32 + nt * 8 + r;
            Bh[nt][0] = packbf(Bs[s][2 * c][n], Bs[s][2 * c + 1][n]);
            Bh[nt][1] = packbf(Bs[s][2 * c + 8][n], Bs[s][2 * c + 9][n]);
        }
#pragma unroll
        for (int mt = 0; mt < 4; mt++)
#pragma unroll
            for (int nt = 0; nt < 4; nt++) {
                mma_bf16(acc[mt][nt], Ah[mt][0], Ah[mt][1], Ah[mt][2], Ah[mt][3],
                         Bh[nt][0], Bh[nt][1]);
            }
        __syncthreads();
    }

#pragma unroll
    for (int mt = 0; mt < 4; mt++) {
        int row0 = rowBase + warpM * 64 + mt * 16 + r;
#pragma unroll
        for (int nt = 0; nt < 4; nt++) {
            int col = colLocal + warpN * 32 + nt * 8 + 2 * c;
            float b0 = bias[col], b1 = bias[col + 1];
            if (row0 < M) {
                float2 o = make_float2(acc[mt][nt][0] + b0, acc[mt][nt][1] + b1);
                *(float2*)&C[(size_t)row0 * Nc + col] = o;
            }
            if (row0 + 8 < M) {
                float2 o = make_float2(acc[mt][nt][2] + b0, acc[mt][nt][3] + b1);
                *(float2*)&C[(size_t)(row0 + 8) * Nc + col] = o;
            }
        }
    }
}

// --------------- fused GATv2 layer, online softmax (layers 1 & 2) -----------
// One warp per destination node.  Lane L: head h=L/4, sub=L%4, float4 cols
// f0+4c (f0 = 12h+sub, c=0..2).  Single pass, 1-deep register prefetch.
template <bool FUSE_L3>
__global__ __launch_bounds__(256) void gat_fused_kernel(
    const float* __restrict__ xl, const float* __restrict__ xr,
    const float* __restrict__ att, const float* __restrict__ bias,
    const int* __restrict__ rowptr, const int* __restrict__ eperm,
    float* __restrict__ outFeat,
    const float* __restrict__ Wl3, const float* __restrict__ bl3,
    const float* __restrict__ Wr3, const float* __restrict__ br3,
    float* __restrict__ xl3, float* __restrict__ xr3,
    int nN) {
    int warp = (blockIdx.x * blockDim.x + threadIdx.x) >> 5;
    if (warp >= nN) return;
    const int L = threadIdx.x & 31;
    const int sub = L & 3;
    const int f0 = 12 * (L >> 2) + sub;
    const int leader = L & ~3;

    const float4* xl4 = (const float4*)xl;
    const float4* xr4 = (const float4*)xr;
    const float4* att4 = (const float4*)att;
    const float4* bias4 = (const float4*)bias;

    float4 rxr[3], ratt[3];
#pragma unroll
    for (int cc = 0; cc < 3; cc++) {
        rxr[cc] = xr4[(size_t)warp * 96 + f0 + 4 * cc];
        ratt[cc] = att4[f0 + 4 * cc];
    }

    const int s0 = rowptr[warp];
    const int s1 = rowptr[warp + 1];

    float m = -FLT_MAX, d = 0.f;
    float4 acc[3];
#pragma unroll
    for (int cc = 0; cc < 3; cc++) acc[cc] = make_float4(0.f, 0.f, 0.f, 0.f);

    float4 nxt[3];
    {
        int sN = eperm[s0];
#pragma unroll
        for (int cc = 0; cc < 3; cc++) nxt[cc] = xl4[(size_t)sN * 96 + f0 + 4 * cc];
    }

    for (int e = s0; e < s1; e++) {
        float4 cur[3];
#pragma unroll
        for (int cc = 0; cc < 3; cc++) cur[cc] = nxt[cc];
        if (e + 1 < s1) {
            int sN = eperm[e + 1];
#pragma unroll
            for (int cc = 0; cc < 3; cc++) nxt[cc] = xl4[(size_t)sN * 96 + f0 + 4 * cc];
        }

        float p = 0.f;
#pragma unroll
        for (int cc = 0; cc < 3; cc++) {
            float4 a = cur[cc], rr = rxr[cc], w = ratt[cc];
            float v;
            v = a.x + rr.x; p += (v > 0.f ? v : NEG * v) * w.x;
            v = a.y + rr.y; p += (v > 0.f ? v : NEG * v) * w.y;
            v = a.z + rr.z; p += (v > 0.f ? v : NEG * v) * w.z;
            v = a.w + rr.w; p += (v > 0.f ? v : NEG * v) * w.w;
        }
        p += __shfl_down_sync(0xffffffffu, p, 2);
        p += __shfl_down_sync(0xffffffffu, p, 1);

        float scale, w;
        if (sub == 0) {
            float mn = fmaxf(m, p);
            scale = __expf(m - mn);
            w = __expf(p - mn);
            d = d * scale + w;
            m = mn;
        }
        scale = __shfl_sync(0xffffffffu, scale, leader);
        w = __shfl_sync(0xffffffffu, w, leader);

#pragma unroll
        for (int cc = 0; cc < 3; cc++) {
            acc[cc].x = acc[cc].x * scale + w * cur[cc].x;
            acc[cc].y = acc[cc].y * scale + w * cur[cc].y;
            acc[cc].z = acc[cc].z * scale + w * cur[cc].z;
            acc[cc].w = acc[cc].w * scale + w * cur[cc].w;
        }
    }

    float inv;
    if (sub == 0) inv = 1.f / (d + 1e-16f);
    inv = __shfl_sync(0xffffffffu, inv, leader);

    float pl0 = 0.f, pl1 = 0.f, pr0 = 0.f, pr1 = 0.f;

#pragma unroll
    for (int cc = 0; cc < 3; cc++) {
        float4 b = bias4[f0 + 4 * cc];
        float4 o;
        o.x = acc[cc].x * inv + b.x; o.x = o.x > 0.f ? o.x : expm1f(o.x);
        o.y = acc[cc].y * inv + b.y; o.y = o.y > 0.f ? o.y : expm1f(o.y);
        o.z = acc[cc].z * inv + b.z; o.z = o.z > 0.f ? o.z : expm1f(o.z);
        o.w = acc[cc].w * inv + b.w; o.w = o.w > 0.f ? o.w : expm1f(o.w);
        if (!FUSE_L3) {
            ((float4*)outFeat)[(size_t)warp * 96 + f0 + 4 * cc] = o;
        } else {
            const int colBase = 4 * (f0 + 4 * cc);
            float ov[4] = {o.x, o.y, o.z, o.w};
#pragma unroll
            for (int j = 0; j < 4; j++) {
                float2 wl = *(const float2*)&Wl3[2 * (colBase + j)];
                float2 wr = *(const float2*)&Wr3[2 * (colBase + j)];
                pl0 += ov[j] * wl.x;
                pl1 += ov[j] * wl.y;
                pr0 += ov[j] * wr.x;
                pr1 += ov[j] * wr.y;
            }
        }
    }

    if (FUSE_L3) {
#pragma unroll
        for (int o = 16; o; o >>= 1) {
            pl0 += __shfl_xor_sync(0xffffffffu, pl0, o);
            pl1 += __shfl_xor_sync(0xffffffffu, pl1, o);
            pr0 += __shfl_xor_sync(0xffffffffu, pr0, o);
            pr1 += __shfl_xor_sync(0xffffffffu, pr1, o);
        }
        if (L == 0) {
            xl3[2 * warp]     = pl0 + bl3[0];
            xl3[2 * warp + 1] = pl1 + bl3[1];
            xr3[2 * warp]     = pr0 + br3[0];
            xr3[2 * warp + 1] = pr1 + br3[1];
        }
    }
}

// ------------------------- layer 3 edge kernel -------------------------------
__global__ void l3_fused_kernel(const float* __restrict__ xl3, const float* __restrict__ xr3,
                                const float* __restrict__ att3, const float* __restrict__ bias3,
                                const int* __restrict__ rowptr, const int* __restrict__ eperm,
                                float* __restrict__ out, int nN) {
    int warp = (blockIdx.x * blockDim.x + threadIdx.x) >> 5;
    if (warp >= nN) return;
    const int L = threadIdx.x & 31;
    const float xr0 = xr3[2 * warp], xr1 = xr3[2 * warp + 1];
    const float a0 = att3[0], a1 = att3[1];
    const int s0 = rowptr[warp], s1 = rowptr[warp + 1];

    float mx = -FLT_MAX;
    for (int e = s0 + L; e < s1; e += 32) {
        int s = eperm[e];
        float m0 = xl3[2 * s] + xr0;
        float m1 = xl3[2 * s + 1] + xr1;
        float sc = (m0 > 0.f ? m0 : NEG * m0) * a0 + (m1 > 0.f ? m1 : NEG * m1) * a1;
        mx = fmaxf(mx, sc);
    }
#pragma unroll
    for (int o = 16; o; o >>= 1) mx = fmaxf(mx, __shfl_xor_sync(0xffffffffu, mx, o));

    float den = 0.f, n0 = 0.f, n1 = 0.f;
    for (int e = s0 + L; e < s1; e += 32) {
        int s = eperm[e];
        float x0 = xl3[2 * s], x1 = xl3[2 * s + 1];
        float m0 = x0 + xr0, m1 = x1 + xr1;
        float sc = (m0 > 0.f ? m0 : NEG * m0) * a0 + (m1 > 0.f ? m1 : NEG * m1) * a1;
        float v = expf(sc - mx);
        den += v;
        n0 += v * x0;
        n1 += v * x1;
    }
#pragma unroll
    for (int o = 16; o; o >>= 1) {
        den += __shfl_xor_sync(0xffffffffu, den, o);
        n0 += __shfl_xor_sync(0xffffffffu, n0, o);
        n1 += __shfl_xor_sync(0xffffffffu, n1, o);
    }
    if (L == 0) {
        float id = 1.f / (den + 1e-16f);
        float z0 = n0 * id + bias3[0];
        float z1 = n1 * id + bias3[1];
        float m = fmaxf(z0, z1);
        float l = m + logf(expf(z0 - m) + expf(z1 - m));
        out[2 * warp] = z0 - l;
        out[2 * warp + 1] = z1 - l;
    }
}

// ------------------------------ host ----------------------------------------
extern "C" void kernel_launch(void* const* d_in, const int* in_sizes, int n_in,
                              void* d_out, int out_size) {
    const float* x     = (const float*)d_in[0];
    const int*   eidx  = (const int*)d_in[1];
    const float* Wl1   = (const float*)d_in[2];
    const float* bl1   = (const float*)d_in[3];
    const float* Wr1   = (const float*)d_in[4];
    const float* br1   = (const float*)d_in[5];
    const float* att1  = (const float*)d_in[6];
    const float* bias1 = (const float*)d_in[7];
    const float* Wl2   = (const float*)d_in[8];
    const float* bl2   = (const float*)d_in[9];
    const float* Wr2   = (const float*)d_in[10];
    const float* br2   = (const float*)d_in[11];
    const float* att2  = (const float*)d_in[12];
    const float* bias2 = (const float*)d_in[13];
    const float* Wl3   = (const float*)d_in[14];
    const float* bl3   = (const float*)d_in[15];
    const float* Wr3   = (const float*)d_in[16];
    const float* br3   = (const float*)d_in[17];
    const float* att3  = (const float*)d_in[18];
    const float* bias3 = (const float*)d_in[19];

    const int nN = in_sizes[0] / 128;
    const int nE = in_sizes[1] / 2;
    const int nEt = nE + nN;
    const int* srcArr = eidx;
    const int* dstArr = eidx + nE;

    float* xl;     cudaGetSymbolAddress((void**)&xl, g_xl);
    float* xr;     cudaGetSymbolAddress((void**)&xr, g_xr);
    float* feat;   cudaGetSymbolAddress((void**)&feat, g_feat);
    int* deg;      cudaGetSymbolAddress((void**)&deg, g_deg);
    int* rowptr;   cudaGetSymbolAddress((void**)&rowptr, g_rowptr);
    int* pos;      cudaGetSymbolAddress((void**)&pos, g_pos);
    int* eperm;    cudaGetSymbolAddress((void**)&eperm, g_eperm);
    int* bsum;     cudaGetSymbolAddress((void**)&bsum, g_bsum);
    float* xl3;    cudaGetSymbolAddress((void**)&xl3, g_xl3);
    float* xr3;    cudaGetSymbolAddress((void**)&xr3, g_xr3);

    const int nb = (nN + 255) / 256;

    // ----- CSR build (reused by all 3 layers) -----
    deg_init_kernel<<<nb, 256>>>(deg, nN);
    deg_hist_kernel<<<(nE + 255) / 256, 256>>>(dstArr, deg, nE);
    scan_block_sums<<<nb, 256>>>(deg, bsum, nN);
    scan_bsum_kernel<<<1, 256>>>(bsum, nb);
    scan_final_kernel<<<nb, 256>>>(deg, bsum, rowptr, pos, nN, nEt);
    scatter_kernel<<<(nEt + 255) / 256, 256>>>(srcArr, dstArr, pos, eperm, nE, nN);

    const dim3 gemmGrd(2 * (HID / 128), (nN + 127) / 128);
    const int fusedGrid = (nN + 7) / 8;

    // ----- layer 1 -----
    gemm_dual_bf16_kernel<<<gemmGrd, 256>>>(x, Wl1, Wr1, bl1, br1, xl, xr, nN, 128, HID);
    gat_fused_kernel<false><<<fusedGrid, 256>>>(xl, xr, att1, bias1, rowptr, eperm,
                                                feat, nullptr, nullptr, nullptr, nullptr,
                                                nullptr, nullptr, nN);

    // ----- layer 2 (+ fused layer-3 transform) -----
    gemm_dual_bf16_kernel<<<gemmGrd, 256>>>(feat, Wl2, Wr2, bl2, br2, xl, xr, nN, HID, HID);
    gat_fused_kernel<true><<<fusedGrid, 256>>>(xl, xr, att2, bias2, rowptr, eperm,
                                               nullptr, Wl3, bl3, Wr3, br3,
                                               xl3, xr3, nN);

    // ----- layer 3 -----
    l3_fused_kernel<<<fusedGrid, 256>>>(xl3, xr3, att3, bias3, rowptr, eperm,
                                        (float*)d_out, nN);
}

// round 11
// speedup vs baseline: 1.0054x; 1.0054x over previous
#include <cuda_runtime.h>
#include <cstdint>
#include <cfloat>

// ---------------------------------------------------------------------------
// GATv2 3-layer forward.  CSR + online-softmax fused edges + 1xTF32 MMA.
// Edge kernel: xor-butterfly softmax (no broadcast shuffles) + 2-deep
// explicitly-named prefetch buffers (no dynamic register indexing).
// N=50000, E=500000 (+N self loops), F_IN=128, HID=384 (8 heads x 48), OUT=2.
// ---------------------------------------------------------------------------

#define NN_MAX 50000
#define EE_MAX 500000
#define ET_MAX (EE_MAX + NN_MAX)
#define HID 384
#define NHEAD 8
#define CH 48
#define NEG 0.2f

// ------------------------- scratch (device globals) ------------------------
__device__ float g_xl[NN_MAX * HID];
__device__ float g_xr[NN_MAX * HID];
__device__ float g_feat[NN_MAX * HID];
__device__ int   g_deg[NN_MAX];
__device__ int   g_rowptr[NN_MAX + 1];
__device__ int   g_pos[NN_MAX];
__device__ int   g_eperm[ET_MAX];
__device__ int   g_bsum[256];
__device__ float g_xl3[NN_MAX * 2];
__device__ float g_xr3[NN_MAX * 2];

// ------------------------------ CSR build -----------------------------------
__global__ void deg_init_kernel(int* deg, int nN) {
    int i = blockIdx.x * blockDim.x + threadIdx.x;
    if (i < nN) deg[i] = 1;
}

__global__ void deg_hist_kernel(const int* __restrict__ dst, int* deg, int E) {
    int e = blockIdx.x * blockDim.x + threadIdx.x;
    if (e < E) atomicAdd(&deg[dst[e]], 1);
}

__global__ void scan_block_sums(const int* __restrict__ deg, int* bsum, int nN) {
    __shared__ int sm[256];
    int i = blockIdx.x * 256 + threadIdx.x;
    sm[threadIdx.x] = (i < nN) ? deg[i] : 0;
    __syncthreads();
    for (int o = 128; o; o >>= 1) {
        if (threadIdx.x < o) sm[threadIdx.x] += sm[threadIdx.x + o];
        __syncthreads();
    }
    if (threadIdx.x == 0) bsum[blockIdx.x] = sm[0];
}

__global__ void scan_bsum_kernel(int* bsum, int nb) {
    __shared__ int sm[256];
    int t = threadIdx.x;
    int v = (t < nb) ? bsum[t] : 0;
    sm[t] = v;
    __syncthreads();
    for (int o = 1; o < 256; o <<= 1) {
        int add = (t >= o) ? sm[t - o] : 0;
        __syncthreads();
        sm[t] += add;
        __syncthreads();
    }
    if (t < nb) bsum[t] = sm[t] - v;
}

__global__ void scan_final_kernel(const int* __restrict__ deg, const int* __restrict__ bsum,
                                  int* rowptr, int* pos, int nN, int nEt) {
    __shared__ int sm[256];
    int t = threadIdx.x;
    int i = blockIdx.x * 256 + t;
    int v = (i < nN) ? deg[i] : 0;
    sm[t] = v;
    __syncthreads();
    for (int o = 1; o < 256; o <<= 1) {
        int add = (t >= o) ? sm[t - o] : 0;
        __syncthreads();
        sm[t] += add;
        __syncthreads();
    }
    if (i < nN) {
        int ex = sm[t] - v + bsum[blockIdx.x];
        rowptr[i] = ex;
        pos[i] = ex;
    }
    if (i == 0) rowptr[nN] = nEt;
}

__global__ void scatter_kernel(const int* __restrict__ src, const int* __restrict__ dst,
                               int* pos, int* eperm, int E, int nN) {
    int t = blockIdx.x * blockDim.x + threadIdx.x;
    if (t >= E + nN) return;
    int s, d;
    if (t < E) { s = src[t]; d = dst[t]; } else { s = d = t - E; }
    int p = atomicAdd(&pos[d], 1);
    eperm[p] = s;
}

// ---------------------------- TF32 helpers ----------------------------------
static __device__ __forceinline__ uint32_t f2tf32(float a) {
    uint32_t r;
    asm("cvt.rna.tf32.f32 %0, %1;" : "=r"(r) : "f"(a));
    return r;
}
static __device__ __forceinline__ void mma_tf32(float c[4], uint32_t a0, uint32_t a1,
                                                uint32_t a2, uint32_t a3,
                                                uint32_t b0, uint32_t b1) {
    asm volatile(
        "mma.sync.aligned.m16n8k8.row.col.f32.tf32.tf32.f32 "
        "{%0,%1,%2,%3}, {%4,%5,%6,%7}, {%8,%9}, {%0,%1,%2,%3};\n"
        : "+f"(c[0]), "+f"(c[1]), "+f"(c[2]), "+f"(c[3])
        : "r"(a0), "r"(a1), "r"(a2), "r"(a3), "r"(b0), "r"(b1));
}
static __device__ __forceinline__ void cpasync16(uint32_t dst, const void* src, int sz) {
    asm volatile("cp.async.cg.shared.global [%0], [%1], 16, %2;\n"
                 :: "r"(dst), "l"(src), "r"(sz));
}
static __device__ __forceinline__ void cpcommit() {
    asm volatile("cp.async.commit_group;\n");
}
template <int N>
static __device__ __forceinline__ void cpwait() {
    asm volatile("cp.async.wait_group %0;\n" :: "n"(N));
}

// -------------------- dual GEMM (xl and xr in one launch) --------------------
__global__ __launch_bounds__(256, 2) void gemm_dual_tf32_kernel(
    const float* __restrict__ A,
    const float* __restrict__ Bl, const float* __restrict__ Br,
    const float* __restrict__ bl, const float* __restrict__ br,
    float* __restrict__ Cl, float* __restrict__ Cr,
    int M, int K, int Nc) {
    __shared__ float As[2][128][20];
    __shared__ float Bs[2][16][136];

    const int tid = threadIdx.x;
    const int lane = tid & 31;
    const int warpId = tid >> 5;
    const int warpM = warpId & 1;
    const int warpN = warpId >> 1;
    const int r = lane >> 2;
    const int c = lane & 3;

    const int nb = Nc >> 7;
    const int half = blockIdx.x / nb;
    const int colLocal = (blockIdx.x - half * nb) * 128;
    const int rowBase = blockIdx.y * 128;
    const float* B = half ? Br : Bl;
    const float* bias = half ? br : bl;
    float* C = half ? Cr : Cl;

    float acc[4][4][4];
#pragma unroll
    for (int i = 0; i < 4; i++)
#pragma unroll
        for (int j = 0; j < 4; j++)
#pragma unroll
            for (int k = 0; k < 4; k++) acc[i][j][k] = 0.f;

    int arow[2], akq[2], bk[2], bnq[2];
#pragma unroll
    for (int j = 0; j < 2; j++) {
        int s = tid * 2 + j;
        arow[j] = s >> 2;  akq[j] = (s & 3) << 2;
        bk[j] = s >> 5;    bnq[j] = (s & 31) << 2;
    }

    const int T = K >> 4;

    auto issue_tile = [&](int t, int s) {
#pragma unroll
        for (int j = 0; j < 2; j++) {
            int gr = rowBase + arow[j];
            int grc = gr < M ? gr : (M - 1);
            const float* gp = A + (size_t)grc * K + t * 16 + akq[j];
            uint32_t sa = (uint32_t)__cvta_generic_to_shared(&As[s][arow[j]][akq[j]]);
            cpasync16(sa, gp, gr < M ? 16 : 0);
        }
#pragma unroll
        for (int j = 0; j < 2; j++) {
            const float* gp = B + (size_t)(t * 16 + bk[j]) * Nc + colLocal + bnq[j];
            uint32_t sa = (uint32_t)__cvta_generic_to_shared(&Bs[s][bk[j]][bnq[j]]);
            cpasync16(sa, gp, 16);
        }
        cpcommit();
    };

    issue_tile(0, 0);

    for (int t = 0; t < T; t++) {
        int s = t & 1;
        if (t + 1 < T) {
            issue_tile(t + 1, s ^ 1);
            cpwait<1>();
        } else {
            cpwait<0>();
        }
        __syncthreads();

#pragma unroll
        for (int kk = 0; kk < 16; kk += 8) {
            uint32_t Ah[4][4], Bh[4][2];
#pragma unroll
            for (int mt = 0; mt < 4; mt++) {
                int m = warpM * 64 + mt * 16 + r;
                Ah[mt][0] = f2tf32(As[s][m][kk + c]);
                Ah[mt][1] = f2tf32(As[s][m + 8][kk + c]);
                Ah[mt][2] = f2tf32(As[s][m][kk + c + 4]);
                Ah[mt][3] = f2tf32(As[s][m + 8][kk + c + 4]);
            }
#pragma unroll
            for (int nt = 0; nt < 4; nt++) {
                int n = warpN * 32 + nt * 8 + r;
                Bh[nt][0] = f2tf32(Bs[s][kk + c][n]);
                Bh[nt][1] = f2tf32(Bs[s][kk + c + 4][n]);
            }
#pragma unroll
            for (int mt = 0; mt < 4; mt++)
#pragma unroll
                for (int nt = 0; nt < 4; nt++) {
                    mma_tf32(acc[mt][nt], Ah[mt][0], Ah[mt][1], Ah[mt][2], Ah[mt][3],
                             Bh[nt][0], Bh[nt][1]);
                }
        }
        __syncthreads();
    }

#pragma unroll
    for (int mt = 0; mt < 4; mt++) {
        int row0 = rowBase + warpM * 64 + mt * 16 + r;
#pragma unroll
        for (int nt = 0; nt < 4; nt++) {
            int col = colLocal + warpN * 32 + nt * 8 + 2 * c;
            float b0 = bias[col], b1 = bias[col + 1];
            if (row0 < M) {
                float2 o = make_float2(acc[mt][nt][0] + b0, acc[mt][nt][1] + b1);
                *(float2*)&C[(size_t)row0 * Nc + col] = o;
            }
            if (row0 + 8 < M) {
                float2 o = make_float2(acc[mt][nt][2] + b0, acc[mt][nt][3] + b1);
                *(float2*)&C[(size_t)(row0 + 8) * Nc + col] = o;
            }
        }
    }
}

// --------------- fused GATv2 layer, online softmax (layers 1 & 2) -----------
// One warp per destination node.  Lane L: head h=L/4, sub=L%4, float4 cols
// f0+4cc (f0 = 12h+sub, cc=0..2).  Single pass.  Quad score reduced via
// xor-butterfly so ALL lanes hold it -> no broadcast shuffles, no divergent
// branch on the critical path.  2-deep prefetch with named buffers.
template <bool FUSE_L3>
__global__ __launch_bounds__(256, 2) void gat_fused_kernel(
    const float* __restrict__ xl, const float* __restrict__ xr,
    const float* __restrict__ att, const float* __restrict__ bias,
    const int* __restrict__ rowptr, const int* __restrict__ eperm,
    float* __restrict__ outFeat,
    const float* __restrict__ Wl3, const float* __restrict__ bl3,
    const float* __restrict__ Wr3, const float* __restrict__ br3,
    float* __restrict__ xl3, float* __restrict__ xr3,
    int nN) {
    int warp = (blockIdx.x * blockDim.x + threadIdx.x) >> 5;
    if (warp >= nN) return;
    const int L = threadIdx.x & 31;
    const int sub = L & 3;
    const int f0 = 12 * (L >> 2) + sub;

    const float4* xl4 = (const float4*)xl;
    const float4* xr4 = (const float4*)xr;
    const float4* att4 = (const float4*)att;
    const float4* bias4 = (const float4*)bias;

    float4 rxr[3], ratt[3];
#pragma unroll
    for (int cc = 0; cc < 3; cc++) {
        rxr[cc] = xr4[(size_t)warp * 96 + f0 + 4 * cc];
        ratt[cc] = att4[f0 + 4 * cc];
    }

    const int s0 = rowptr[warp];
    const int s1 = rowptr[warp + 1];

    float m = -FLT_MAX, d = 0.f;
    float4 acc[3];
#pragma unroll
    for (int cc = 0; cc < 3; cc++) acc[cc] = make_float4(0.f, 0.f, 0.f, 0.f);

    // process one edge whose row is in cur[]
    auto edge_body = [&](const float4 cur[3]) {
        float p = 0.f;
#pragma unroll
        for (int cc = 0; cc < 3; cc++) {
            float4 a = cur[cc], rr = rxr[cc], w4 = ratt[cc];
            float v;
            v = a.x + rr.x; p += (v > 0.f ? v : NEG * v) * w4.x;
            v = a.y + rr.y; p += (v > 0.f ? v : NEG * v) * w4.y;
            v = a.z + rr.z; p += (v > 0.f ? v : NEG * v) * w4.z;
            v = a.w + rr.w; p += (v > 0.f ? v : NEG * v) * w4.w;
        }
        p += __shfl_xor_sync(0xffffffffu, p, 2);
        p += __shfl_xor_sync(0xffffffffu, p, 1);
        // every lane of the quad now has the head score; redundantly update
        float mn = fmaxf(m, p);
        float scale = __expf(m - mn);
        float w = __expf(p - mn);
        d = d * scale + w;
        m = mn;
#pragma unroll
        for (int cc = 0; cc < 3; cc++) {
            acc[cc].x = acc[cc].x * scale + w * cur[cc].x;
            acc[cc].y = acc[cc].y * scale + w * cur[cc].y;
            acc[cc].z = acc[cc].z * scale + w * cur[cc].z;
            acc[cc].w = acc[cc].w * scale + w * cur[cc].w;
        }
    };

    float4 bufA[3], bufB[3];
    {
        int sN = eperm[s0];
#pragma unroll
        for (int cc = 0; cc < 3; cc++) bufA[cc] = xl4[(size_t)sN * 96 + f0 + 4 * cc];
        if (s0 + 1 < s1) {
            sN = eperm[s0 + 1];
#pragma unroll
            for (int cc = 0; cc < 3; cc++) bufB[cc] = xl4[(size_t)sN * 96 + f0 + 4 * cc];
        }
    }

    for (int e = s0; e < s1; e += 2) {
        float4 cur[3];
#pragma unroll
        for (int cc = 0; cc < 3; cc++) cur[cc] = bufA[cc];
        if (e + 2 < s1) {
            int sN = eperm[e + 2];
#pragma unroll
            for (int cc = 0; cc < 3; cc++) bufA[cc] = xl4[(size_t)sN * 96 + f0 + 4 * cc];
        }
        edge_body(cur);

        if (e + 1 < s1) {
#pragma unroll
            for (int cc = 0; cc < 3; cc++) cur[cc] = bufB[cc];
            if (e + 3 < s1) {
                int sN = eperm[e + 3];
#pragma unroll
                for (int cc = 0; cc < 3; cc++) bufB[cc] = xl4[(size_t)sN * 96 + f0 + 4 * cc];
            }
            edge_body(cur);
        }
    }

    const float inv = 1.f / (d + 1e-16f);

    float pl0 = 0.f, pl1 = 0.f, pr0 = 0.f, pr1 = 0.f;

#pragma unroll
    for (int cc = 0; cc < 3; cc++) {
        float4 b = bias4[f0 + 4 * cc];
        float4 o;
        o.x = acc[cc].x * inv + b.x; o.x = o.x > 0.f ? o.x : expm1f(o.x);
        o.y = acc[cc].y * inv + b.y; o.y = o.y > 0.f ? o.y : expm1f(o.y);
        o.z = acc[cc].z * inv + b.z; o.z = o.z > 0.f ? o.z : expm1f(o.z);
        o.w = acc[cc].w * inv + b.w; o.w = o.w > 0.f ? o.w : expm1f(o.w);
        if (!FUSE_L3) {
            ((float4*)outFeat)[(size_t)warp * 96 + f0 + 4 * cc] = o;
        } else {
            const int colBase = 4 * (f0 + 4 * cc);
            float ov[4] = {o.x, o.y, o.z, o.w};
#pragma unroll
            for (int j = 0; j < 4; j++) {
                float2 wl = *(const float2*)&Wl3[2 * (colBase + j)];
                float2 wr = *(const float2*)&Wr3[2 * (colBase + j)];
                pl0 += ov[j] * wl.x;
                pl1 += ov[j] * wl.y;
                pr0 += ov[j] * wr.x;
                pr1 += ov[j] * wr.y;
            }
        }
    }

    if (FUSE_L3) {
#pragma unroll
        for (int o = 16; o; o >>= 1) {
            pl0 += __shfl_xor_sync(0xffffffffu, pl0, o);
            pl1 += __shfl_xor_sync(0xffffffffu, pl1, o);
            pr0 += __shfl_xor_sync(0xffffffffu, pr0, o);
            pr1 += __shfl_xor_sync(0xffffffffu, pr1, o);
        }
        if (L == 0) {
            xl3[2 * warp]     = pl0 + bl3[0];
            xl3[2 * warp + 1] = pl1 + bl3[1];
            xr3[2 * warp]     = pr0 + br3[0];
            xr3[2 * warp + 1] = pr1 + br3[1];
        }
    }
}

// ------------------------- layer 3 edge kernel -------------------------------
__global__ void l3_fused_kernel(const float* __restrict__ xl3, const float* __restrict__ xr3,
                                const float* __restrict__ att3, const float* __restrict__ bias3,
                                const int* __restrict__ rowptr, const int* __restrict__ eperm,
                                float* __restrict__ out, int nN) {
    int warp = (blockIdx.x * blockDim.x + threadIdx.x) >> 5;
    if (warp >= nN) return;
    const int L = threadIdx.x & 31;
    const float xr0 = xr3[2 * warp], xr1 = xr3[2 * warp + 1];
    const float a0 = att3[0], a1 = att3[1];
    const int s0 = rowptr[warp], s1 = rowptr[warp + 1];

    float mx = -FLT_MAX;
    for (int e = s0 + L; e < s1; e += 32) {
        int s = eperm[e];
        float m0 = xl3[2 * s] + xr0;
        float m1 = xl3[2 * s + 1] + xr1;
        float sc = (m0 > 0.f ? m0 : NEG * m0) * a0 + (m1 > 0.f ? m1 : NEG * m1) * a1;
        mx = fmaxf(mx, sc);
    }
#pragma unroll
    for (int o = 16; o; o >>= 1) mx = fmaxf(mx, __shfl_xor_sync(0xffffffffu, mx, o));

    float den = 0.f, n0 = 0.f, n1 = 0.f;
    for (int e = s0 + L; e < s1; e += 32) {
        int s = eperm[e];
        float x0 = xl3[2 * s], x1 = xl3[2 * s + 1];
        float m0 = x0 + xr0, m1 = x1 + xr1;
        float sc = (m0 > 0.f ? m0 : NEG * m0) * a0 + (m1 > 0.f ? m1 : NEG * m1) * a1;
        float v = expf(sc - mx);
        den += v;
        n0 += v * x0;
        n1 += v * x1;
    }
#pragma unroll
    for (int o = 16; o; o >>= 1) {
        den += __shfl_xor_sync(0xffffffffu, den, o);
        n0 += __shfl_xor_sync(0xffffffffu, n0, o);
        n1 += __shfl_xor_sync(0xffffffffu, n1, o);
    }
    if (L == 0) {
        float id = 1.f / (den + 1e-16f);
        float z0 = n0 * id + bias3[0];
        float z1 = n1 * id + bias3[1];
        float m = fmaxf(z0, z1);
        float l = m + logf(expf(z0 - m) + expf(z1 - m));
        out[2 * warp] = z0 - l;
        out[2 * warp + 1] = z1 - l;
    }
}

// ------------------------------ host ----------------------------------------
extern "C" void kernel_launch(void* const* d_in, const int* in_sizes, int n_in,
                              void* d_out, int out_size) {
    const float* x     = (const float*)d_in[0];
    const int*   eidx  = (const int*)d_in[1];
    const float* Wl1   = (const float*)d_in[2];
    const float* bl1   = (const float*)d_in[3];
    const float* Wr1   = (const float*)d_in[4];
    const float* br1   = (const float*)d_in[5];
    const float* att1  = (const float*)d_in[6];
    const float* bias1 = (const float*)d_in[7];
    const float* Wl2   = (const float*)d_in[8];
    const float* bl2   = (const float*)d_in[9];
    const float* Wr2   = (const float*)d_in[10];
    const float* br2   = (const float*)d_in[11];
    const float* att2  = (const float*)d_in[12];
    const float* bias2 = (const float*)d_in[13];
    const float* Wl3   = (const float*)d_in[14];
    const float* bl3   = (const float*)d_in[15];
    const float* Wr3   = (const float*)d_in[16];
    const float* br3   = (const float*)d_in[17];
    const float* att3  = (const float*)d_in[18];
    const float* bias3 = (const float*)d_in[19];

    const int nN = in_sizes[0] / 128;
    const int nE = in_sizes[1] / 2;
    const int nEt = nE + nN;
    const int* srcArr = eidx;
    const int* dstArr = eidx + nE;

    float* xl;     cudaGetSymbolAddress((void**)&xl, g_xl);
    float* xr;     cudaGetSymbolAddress((void**)&xr, g_xr);
    float* feat;   cudaGetSymbolAddress((void**)&feat, g_feat);
    int* deg;      cudaGetSymbolAddress((void**)&deg, g_deg);
    int* rowptr;   cudaGetSymbolAddress((void**)&rowptr, g_rowptr);
    int* pos;      cudaGetSymbolAddress((void**)&pos, g_pos);
    int* eperm;    cudaGetSymbolAddress((void**)&eperm, g_eperm);
    int* bsum;     cudaGetSymbolAddress((void**)&bsum, g_bsum);
    float* xl3;    cudaGetSymbolAddress((void**)&xl3, g_xl3);
    float* xr3;    cudaGetSymbolAddress((void**)&xr3, g_xr3);

    const int nb = (nN + 255) / 256;

    // ----- CSR build (reused by all 3 layers) -----
    deg_init_kernel<<<nb, 256>>>(deg, nN);
    deg_hist_kernel<<<(nE + 255) / 256, 256>>>(dstArr, deg, nE);
    scan_block_sums<<<nb, 256>>>(deg, bsum, nN);
    scan_bsum_kernel<<<1, 256>>>(bsum, nb);
    scan_final_kernel<<<nb, 256>>>(deg, bsum, rowptr, pos, nN, nEt);
    scatter_kernel<<<(nEt + 255) / 256, 256>>>(srcArr, dstArr, pos, eperm, nE, nN);

    const dim3 gemmGrd(2 * (HID / 128), (nN + 127) / 128);
    const int fusedGrid = (nN + 7) / 8;

    // ----- layer 1 -----
    gemm_dual_tf32_kernel<<<gemmGrd, 256>>>(x, Wl1, Wr1, bl1, br1, xl, xr, nN, 128, HID);
    gat_fused_kernel<false><<<fusedGrid, 256>>>(xl, xr, att1, bias1, rowptr, eperm,
                                                feat, nullptr, nullptr, nullptr, nullptr,
                                                nullptr, nullptr, nN);

    // ----- layer 2 (+ fused layer-3 transform) -----
    gemm_dual_tf32_kernel<<<gemmGrd, 256>>>(feat, Wl2, Wr2, bl2, br2, xl, xr, nN, HID, HID);
    gat_fused_kernel<true><<<fusedGrid, 256>>>(xl, xr, att2, bias2, rowptr, eperm,
                                               nullptr, Wl3, bl3, Wr3, br3,
                                               xl3, xr3, nN);

    // ----- layer 3 -----
    l3_fused_kernel<<<fusedGrid, 256>>>(xl3, xr3, att3, bias3, rowptr, eperm,
                                        (float*)d_out, nN);
}

// round 13
// speedup vs baseline: 1.0866x; 1.0807x over previous
#include <cuda_runtime.h>
#include <cstdint>
#include <cfloat>

// ---------------------------------------------------------------------------
// GATv2 3-layer forward.  CSR + online-softmax fused edges + 1xTF32 MMA.
// R7 kernels; CSR build forked onto a side stream to overlap with GEMM1.
// N=50000, E=500000 (+N self loops), F_IN=128, HID=384 (8 heads x 48), OUT=2.
// ---------------------------------------------------------------------------

#define NN_MAX 50000
#define EE_MAX 500000
#define ET_MAX (EE_MAX + NN_MAX)
#define HID 384
#define NHEAD 8
#define CH 48
#define NEG 0.2f

// ------------------------- scratch (device globals) ------------------------
__device__ float g_xl[NN_MAX * HID];
__device__ float g_xr[NN_MAX * HID];
__device__ float g_feat[NN_MAX * HID];
__device__ int   g_deg[NN_MAX];
__device__ int   g_rowptr[NN_MAX + 1];
__device__ int   g_pos[NN_MAX];
__device__ int   g_eperm[ET_MAX];
__device__ int   g_bsum[256];
__device__ float g_xl3[NN_MAX * 2];
__device__ float g_xr3[NN_MAX * 2];

// ---------------- side stream / events (created at program load) ------------
namespace {
struct ForkResources {
    cudaStream_t s2 = nullptr;
    cudaEvent_t evFork = nullptr, evJoin = nullptr;
    bool ok = false;
    ForkResources() {
        ok = (cudaStreamCreateWithFlags(&s2, cudaStreamNonBlocking) == cudaSuccess)
          && (cudaEventCreateWithFlags(&evFork, cudaEventDisableTiming) == cudaSuccess)
          && (cudaEventCreateWithFlags(&evJoin, cudaEventDisableTiming) == cudaSuccess);
    }
};
ForkResources g_fork;   // static init before harness checkpoints
}

// ------------------------------ CSR build -----------------------------------
__global__ void deg_init_kernel(int* deg, int nN) {
    int i = blockIdx.x * blockDim.x + threadIdx.x;
    if (i < nN) deg[i] = 1;
}

__global__ void deg_hist_kernel(const int* __restrict__ dst, int* deg, int E) {
    int e = blockIdx.x * blockDim.x + threadIdx.x;
    if (e < E) atomicAdd(&deg[dst[e]], 1);
}

__global__ void scan_block_sums(const int* __restrict__ deg, int* bsum, int nN) {
    __shared__ int sm[256];
    int i = blockIdx.x * 256 + threadIdx.x;
    sm[threadIdx.x] = (i < nN) ? deg[i] : 0;
    __syncthreads();
    for (int o = 128; o; o >>= 1) {
        if (threadIdx.x < o) sm[threadIdx.x] += sm[threadIdx.x + o];
        __syncthreads();
    }
    if (threadIdx.x == 0) bsum[blockIdx.x] = sm[0];
}

__global__ void scan_bsum_kernel(int* bsum, int nb) {
    __shared__ int sm[256];
    int t = threadIdx.x;
    int v = (t < nb) ? bsum[t] : 0;
    sm[t] = v;
    __syncthreads();
    for (int o = 1; o < 256; o <<= 1) {
        int add = (t >= o) ? sm[t - o] : 0;
        __syncthreads();
        sm[t] += add;
        __syncthreads();
    }
    if (t < nb) bsum[t] = sm[t] - v;
}

__global__ void scan_final_kernel(const int* __restrict__ deg, const int* __restrict__ bsum,
                                  int* rowptr, int* pos, int nN, int nEt) {
    __shared__ int sm[256];
    int t = threadIdx.x;
    int i = blockIdx.x * 256 + t;
    int v = (i < nN) ? deg[i] : 0;
    sm[t] = v;
    __syncthreads();
    for (int o = 1; o < 256; o <<= 1) {
        int add = (t >= o) ? sm[t - o] : 0;
        __syncthreads();
        sm[t] += add;
        __syncthreads();
    }
    if (i < nN) {
        int ex = sm[t] - v + bsum[blockIdx.x];
        rowptr[i] = ex;
        pos[i] = ex;
    }
    if (i == 0) rowptr[nN] = nEt;
}

__global__ void scatter_kernel(const int* __restrict__ src, const int* __restrict__ dst,
                               int* pos, int* eperm, int E, int nN) {
    int t = blockIdx.x * blockDim.x + threadIdx.x;
    if (t >= E + nN) return;
    int s, d;
    if (t < E) { s = src[t]; d = dst[t]; } else { s = d = t - E; }
    int p = atomicAdd(&pos[d], 1);
    eperm[p] = s;
}

// ---------------------------- TF32 helpers ----------------------------------
static __device__ __forceinline__ uint32_t f2tf32(float a) {
    uint32_t r;
    asm("cvt.rna.tf32.f32 %0, %1;" : "=r"(r) : "f"(a));
    return r;
}
static __device__ __forceinline__ void mma_tf32(float c[4], uint32_t a0, uint32_t a1,
                                                uint32_t a2, uint32_t a3,
                                                uint32_t b0, uint32_t b1) {
    asm volatile(
        "mma.sync.aligned.m16n8k8.row.col.f32.tf32.tf32.f32 "
        "{%0,%1,%2,%3}, {%4,%5,%6,%7}, {%8,%9}, {%0,%1,%2,%3};\n"
        : "+f"(c[0]), "+f"(c[1]), "+f"(c[2]), "+f"(c[3])
        : "r"(a0), "r"(a1), "r"(a2), "r"(a3), "r"(b0), "r"(b1));
}
static __device__ __forceinline__ void cpasync16(uint32_t dst, const void* src, int sz) {
    asm volatile("cp.async.cg.shared.global [%0], [%1], 16, %2;\n"
                 :: "r"(dst), "l"(src), "r"(sz));
}
static __device__ __forceinline__ void cpcommit() {
    asm volatile("cp.async.commit_group;\n");
}
template <int N>
static __device__ __forceinline__ void cpwait() {
    asm volatile("cp.async.wait_group %0;\n" :: "n"(N));
}

// -------------------- dual GEMM (xl and xr in one launch) --------------------
__global__ __launch_bounds__(256, 2) void gemm_dual_tf32_kernel(
    const float* __restrict__ A,
    const float* __restrict__ Bl, const float* __restrict__ Br,
    const float* __restrict__ bl, const float* __restrict__ br,
    float* __restrict__ Cl, float* __restrict__ Cr,
    int M, int K, int Nc) {
    __shared__ float As[2][128][20];
    __shared__ float Bs[2][16][136];

    const int tid = threadIdx.x;
    const int lane = tid & 31;
    const int warpId = tid >> 5;
    const int warpM = warpId & 1;
    const int warpN = warpId >> 1;
    const int r = lane >> 2;
    const int c = lane & 3;

    const int nb = Nc >> 7;
    const int half = blockIdx.x / nb;
    const int colLocal = (blockIdx.x - half * nb) * 128;
    const int rowBase = blockIdx.y * 128;
    const float* B = half ? Br : Bl;
    const float* bias = half ? br : bl;
    float* C = half ? Cr : Cl;

    float acc[4][4][4];
#pragma unroll
    for (int i = 0; i < 4; i++)
#pragma unroll
        for (int j = 0; j < 4; j++)
#pragma unroll
            for (int k = 0; k < 4; k++) acc[i][j][k] = 0.f;

    int arow[2], akq[2], bk[2], bnq[2];
#pragma unroll
    for (int j = 0; j < 2; j++) {
        int s = tid * 2 + j;
        arow[j] = s >> 2;  akq[j] = (s & 3) << 2;
        bk[j] = s >> 5;    bnq[j] = (s & 31) << 2;
    }

    const int T = K >> 4;

    auto issue_tile = [&](int t, int s) {
#pragma unroll
        for (int j = 0; j < 2; j++) {
            int gr = rowBase + arow[j];
            int grc = gr < M ? gr : (M - 1);
            const float* gp = A + (size_t)grc * K + t * 16 + akq[j];
            uint32_t sa = (uint32_t)__cvta_generic_to_shared(&As[s][arow[j]][akq[j]]);
            cpasync16(sa, gp, gr < M ? 16 : 0);
        }
#pragma unroll
        for (int j = 0; j < 2; j++) {
            const float* gp = B + (size_t)(t * 16 + bk[j]) * Nc + colLocal + bnq[j];
            uint32_t sa = (uint32_t)__cvta_generic_to_shared(&Bs[s][bk[j]][bnq[j]]);
            cpasync16(sa, gp, 16);
        }
        cpcommit();
    };

    issue_tile(0, 0);

    for (int t = 0; t < T; t++) {
        int s = t & 1;
        if (t + 1 < T) {
            issue_tile(t + 1, s ^ 1);
            cpwait<1>();
        } else {
            cpwait<0>();
        }
        __syncthreads();

#pragma unroll
        for (int kk = 0; kk < 16; kk += 8) {
            uint32_t Ah[4][4], Bh[4][2];
#pragma unroll
            for (int mt = 0; mt < 4; mt++) {
                int m = warpM * 64 + mt * 16 + r;
                Ah[mt][0] = f2tf32(As[s][m][kk + c]);
                Ah[mt][1] = f2tf32(As[s][m + 8][kk + c]);
                Ah[mt][2] = f2tf32(As[s][m][kk + c + 4]);
                Ah[mt][3] = f2tf32(As[s][m + 8][kk + c + 4]);
            }
#pragma unroll
            for (int nt = 0; nt < 4; nt++) {
                int n = warpN * 32 + nt * 8 + r;
                Bh[nt][0] = f2tf32(Bs[s][kk + c][n]);
                Bh[nt][1] = f2tf32(Bs[s][kk + c + 4][n]);
            }
#pragma unroll
            for (int mt = 0; mt < 4; mt++)
#pragma unroll
                for (int nt = 0; nt < 4; nt++) {
                    mma_tf32(acc[mt][nt], Ah[mt][0], Ah[mt][1], Ah[mt][2], Ah[mt][3],
                             Bh[nt][0], Bh[nt][1]);
                }
        }
        __syncthreads();
    }

#pragma unroll
    for (int mt = 0; mt < 4; mt++) {
        int row0 = rowBase + warpM * 64 + mt * 16 + r;
#pragma unroll
        for (int nt = 0; nt < 4; nt++) {
            int col = colLocal + warpN * 32 + nt * 8 + 2 * c;
            float b0 = bias[col], b1 = bias[col + 1];
            if (row0 < M) {
                float2 o = make_float2(acc[mt][nt][0] + b0, acc[mt][nt][1] + b1);
                *(float2*)&C[(size_t)row0 * Nc + col] = o;
            }
            if (row0 + 8 < M) {
                float2 o = make_float2(acc[mt][nt][2] + b0, acc[mt][nt][3] + b1);
                *(float2*)&C[(size_t)(row0 + 8) * Nc + col] = o;
            }
        }
    }
}

// --------------- fused GATv2 layer, online softmax (layers 1 & 2) -----------
// R7 form: one warp per destination node; lane L: head h=L/4, sub=L%4, float4
// cols f0+4cc (f0 = 12h+sub).  Single pass, 1-deep register prefetch.
template <bool FUSE_L3>
__global__ __launch_bounds__(256) void gat_fused_kernel(
    const float* __restrict__ xl, const float* __restrict__ xr,
    const float* __restrict__ att, const float* __restrict__ bias,
    const int* __restrict__ rowptr, const int* __restrict__ eperm,
    float* __restrict__ outFeat,
    const float* __restrict__ Wl3, const float* __restrict__ bl3,
    const float* __restrict__ Wr3, const float* __restrict__ br3,
    float* __restrict__ xl3, float* __restrict__ xr3,
    int nN) {
    int warp = (blockIdx.x * blockDim.x + threadIdx.x) >> 5;
    if (warp >= nN) return;
    const int L = threadIdx.x & 31;
    const int sub = L & 3;
    const int f0 = 12 * (L >> 2) + sub;
    const int leader = L & ~3;

    const float4* xl4 = (const float4*)xl;
    const float4* xr4 = (const float4*)xr;
    const float4* att4 = (const float4*)att;
    const float4* bias4 = (const float4*)bias;

    float4 rxr[3], ratt[3];
#pragma unroll
    for (int cc = 0; cc < 3; cc++) {
        rxr[cc] = xr4[(size_t)warp * 96 + f0 + 4 * cc];
        ratt[cc] = att4[f0 + 4 * cc];
    }

    const int s0 = rowptr[warp];
    const int s1 = rowptr[warp + 1];

    float m = -FLT_MAX, d = 0.f;
    float4 acc[3];
#pragma unroll
    for (int cc = 0; cc < 3; cc++) acc[cc] = make_float4(0.f, 0.f, 0.f, 0.f);

    float4 nxt[3];
    {
        int sN = eperm[s0];
#pragma unroll
        for (int cc = 0; cc < 3; cc++) nxt[cc] = xl4[(size_t)sN * 96 + f0 + 4 * cc];
    }

    for (int e = s0; e < s1; e++) {
        float4 cur[3];
#pragma unroll
        for (int cc = 0; cc < 3; cc++) cur[cc] = nxt[cc];
        if (e + 1 < s1) {
            int sN = eperm[e + 1];
#pragma unroll
            for (int cc = 0; cc < 3; cc++) nxt[cc] = xl4[(size_t)sN * 96 + f0 + 4 * cc];
        }

        float p = 0.f;
#pragma unroll
        for (int cc = 0; cc < 3; cc++) {
            float4 a = cur[cc], rr = rxr[cc], w4 = ratt[cc];
            float v;
            v = a.x + rr.x; p += (v > 0.f ? v : NEG * v) * w4.x;
            v = a.y + rr.y; p += (v > 0.f ? v : NEG * v) * w4.y;
            v = a.z + rr.z; p += (v > 0.f ? v : NEG * v) * w4.z;
            v = a.w + rr.w; p += (v > 0.f ? v : NEG * v) * w4.w;
        }
        p += __shfl_down_sync(0xffffffffu, p, 2);
        p += __shfl_down_sync(0xffffffffu, p, 1);

        float scale, w;
        if (sub == 0) {
            float mn = fmaxf(m, p);
            scale = __expf(m - mn);
            w = __expf(p - mn);
            d = d * scale + w;
            m = mn;
        }
        scale = __shfl_sync(0xffffffffu, scale, leader);
        w = __shfl_sync(0xffffffffu, w, leader);

#pragma unroll
        for (int cc = 0; cc < 3; cc++) {
            acc[cc].x = acc[cc].x * scale + w * cur[cc].x;
            acc[cc].y = acc[cc].y * scale + w * cur[cc].y;
            acc[cc].z = acc[cc].z * scale + w * cur[cc].z;
            acc[cc].w = acc[cc].w * scale + w * cur[cc].w;
        }
    }

    float inv;
    if (sub == 0) inv = 1.f / (d + 1e-16f);
    inv = __shfl_sync(0xffffffffu, inv, leader);

    float pl0 = 0.f, pl1 = 0.f, pr0 = 0.f, pr1 = 0.f;

#pragma unroll
    for (int cc = 0; cc < 3; cc++) {
        float4 b = bias4[f0 + 4 * cc];
        float4 o;
        o.x = acc[cc].x * inv + b.x; o.x = o.x > 0.f ? o.x : expm1f(o.x);
        o.y = acc[cc].y * inv + b.y; o.y = o.y > 0.f ? o.y : expm1f(o.y);
        o.z = acc[cc].z * inv + b.z; o.z = o.z > 0.f ? o.z : expm1f(o.z);
        o.w = acc[cc].w * inv + b.w; o.w = o.w > 0.f ? o.w : expm1f(o.w);
        if (!FUSE_L3) {
            ((float4*)outFeat)[(size_t)warp * 96 + f0 + 4 * cc] = o;
        } else {
            const int colBase = 4 * (f0 + 4 * cc);
            float ov[4] = {o.x, o.y, o.z, o.w};
#pragma unroll
            for (int j = 0; j < 4; j++) {
                float2 wl = *(const float2*)&Wl3[2 * (colBase + j)];
                float2 wr = *(const float2*)&Wr3[2 * (colBase + j)];
                pl0 += ov[j] * wl.x;
                pl1 += ov[j] * wl.y;
                pr0 += ov[j] * wr.x;
                pr1 += ov[j] * wr.y;
            }
        }
    }

    if (FUSE_L3) {
#pragma unroll
        for (int o = 16; o; o >>= 1) {
            pl0 += __shfl_xor_sync(0xffffffffu, pl0, o);
            pl1 += __shfl_xor_sync(0xffffffffu, pl1, o);
            pr0 += __shfl_xor_sync(0xffffffffu, pr0, o);
            pr1 += __shfl_xor_sync(0xffffffffu, pr1, o);
        }
        if (L == 0) {
            xl3[2 * warp]     = pl0 + bl3[0];
            xl3[2 * warp + 1] = pl1 + bl3[1];
            xr3[2 * warp]     = pr0 + br3[0];
            xr3[2 * warp + 1] = pr1 + br3[1];
        }
    }
}

// ------------------------- layer 3 edge kernel -------------------------------
__global__ void l3_fused_kernel(const float* __restrict__ xl3, const float* __restrict__ xr3,
                                const float* __restrict__ att3, const float* __restrict__ bias3,
                                const int* __restrict__ rowptr, const int* __restrict__ eperm,
                                float* __restrict__ out, int nN) {
    int warp = (blockIdx.x * blockDim.x + threadIdx.x) >> 5;
    if (warp >= nN) return;
    const int L = threadIdx.x & 31;
    const float xr0 = xr3[2 * warp], xr1 = xr3[2 * warp + 1];
    const float a0 = att3[0], a1 = att3[1];
    const int s0 = rowptr[warp], s1 = rowptr[warp + 1];

    float mx = -FLT_MAX;
    for (int e = s0 + L; e < s1; e += 32) {
        int s = eperm[e];
        float m0 = xl3[2 * s] + xr0;
        float m1 = xl3[2 * s + 1] + xr1;
        float sc = (m0 > 0.f ? m0 : NEG * m0) * a0 + (m1 > 0.f ? m1 : NEG * m1) * a1;
        mx = fmaxf(mx, sc);
    }
#pragma unroll
    for (int o = 16; o; o >>= 1) mx = fmaxf(mx, __shfl_xor_sync(0xffffffffu, mx, o));

    float den = 0.f, n0 = 0.f, n1 = 0.f;
    for (int e = s0 + L; e < s1; e += 32) {
        int s = eperm[e];
        float x0 = xl3[2 * s], x1 = xl3[2 * s + 1];
        float m0 = x0 + xr0, m1 = x1 + xr1;
        float sc = (m0 > 0.f ? m0 : NEG * m0) * a0 + (m1 > 0.f ? m1 : NEG * m1) * a1;
        float v = expf(sc - mx);
        den += v;
        n0 += v * x0;
        n1 += v * x1;
    }
#pragma unroll
    for (int o = 16; o; o >>= 1) {
        den += __shfl_xor_sync(0xffffffffu, den, o);
        n0 += __shfl_xor_sync(0xffffffffu, n0, o);
        n1 += __shfl_xor_sync(0xffffffffu, n1, o);
    }
    if (L == 0) {
        float id = 1.f / (den + 1e-16f);
        float z0 = n0 * id + bias3[0];
        float z1 = n1 * id + bias3[1];
        float m = fmaxf(z0, z1);
        float l = m + logf(expf(z0 - m) + expf(z1 - m));
        out[2 * warp] = z0 - l;
        out[2 * warp + 1] = z1 - l;
    }
}

// ------------------------------ host ----------------------------------------
extern "C" void kernel_launch(void* const* d_in, const int* in_sizes, int n_in,
                              void* d_out, int out_size) {
    const float* x     = (const float*)d_in[0];
    const int*   eidx  = (const int*)d_in[1];
    const float* Wl1   = (const float*)d_in[2];
    const float* bl1   = (const float*)d_in[3];
    const float* Wr1   = (const float*)d_in[4];
    const float* br1   = (const float*)d_in[5];
    const float* att1  = (const float*)d_in[6];
    const float* bias1 = (const float*)d_in[7];
    const float* Wl2   = (const float*)d_in[8];
    const float* bl2   = (const float*)d_in[9];
    const float* Wr2   = (const float*)d_in[10];
    const float* br2   = (const float*)d_in[11];
    const float* att2  = (const float*)d_in[12];
    const float* bias2 = (const float*)d_in[13];
    const float* Wl3   = (const float*)d_in[14];
    const float* bl3   = (const float*)d_in[15];
    const float* Wr3   = (const float*)d_in[16];
    const float* br3   = (const float*)d_in[17];
    const float* att3  = (const float*)d_in[18];
    const float* bias3 = (const float*)d_in[19];

    const int nN = in_sizes[0] / 128;
    const int nE = in_sizes[1] / 2;
    const int nEt = nE + nN;
    const int* srcArr = eidx;
    const int* dstArr = eidx + nE;

    float* xl;     cudaGetSymbolAddress((void**)&xl, g_xl);
    float* xr;     cudaGetSymbolAddress((void**)&xr, g_xr);
    float* feat;   cudaGetSymbolAddress((void**)&feat, g_feat);
    int* deg;      cudaGetSymbolAddress((void**)&deg, g_deg);
    int* rowptr;   cudaGetSymbolAddress((void**)&rowptr, g_rowptr);
    int* pos;      cudaGetSymbolAddress((void**)&pos, g_pos);
    int* eperm;    cudaGetSymbolAddress((void**)&eperm, g_eperm);
    int* bsum;     cudaGetSymbolAddress((void**)&bsum, g_bsum);
    float* xl3;    cudaGetSymbolAddress((void**)&xl3, g_xl3);
    float* xr3;    cudaGetSymbolAddress((void**)&xr3, g_xr3);

    const int nb = (nN + 255) / 256;
    const dim3 gemmGrd(2 * (HID / 128), (nN + 127) / 128);
    const int fusedGrid = (nN + 7) / 8;

    const bool forked = g_fork.ok;
    cudaStream_t sc = forked ? g_fork.s2 : (cudaStream_t)0;

    if (forked) {
        // fork: side stream waits on everything previously on the main stream
        cudaEventRecord(g_fork.evFork, 0);
        cudaStreamWaitEvent(sc, g_fork.evFork, 0);
    }

    // ----- CSR build on side stream (overlaps GEMM1) -----
    deg_init_kernel<<<nb, 256, 0, sc>>>(deg, nN);
    deg_hist_kernel<<<(nE + 255) / 256, 256, 0, sc>>>(dstArr, deg, nE);
    scan_block_sums<<<nb, 256, 0, sc>>>(deg, bsum, nN);
    scan_bsum_kernel<<<1, 256, 0, sc>>>(bsum, nb);
    scan_final_kernel<<<nb, 256, 0, sc>>>(deg, bsum, rowptr, pos, nN, nEt);
    scatter_kernel<<<(nEt + 255) / 256, 256, 0, sc>>>(srcArr, dstArr, pos, eperm, nE, nN);

    // ----- layer-1 GEMM on main stream (independent of CSR) -----
    gemm_dual_tf32_kernel<<<gemmGrd, 256>>>(x, Wl1, Wr1, bl1, br1, xl, xr, nN, 128, HID);

    if (forked) {
        // join: main stream waits for CSR completion
        cudaEventRecord(g_fork.evJoin, sc);
        cudaStreamWaitEvent((cudaStream_t)0, g_fork.evJoin, 0);
    }

    // ----- layer 1 edges -----
    gat_fused_kernel<false><<<fusedGrid, 256>>>(xl, xr, att1, bias1, rowptr, eperm,
                                                feat, nullptr, nullptr, nullptr, nullptr,
                                                nullptr, nullptr, nN);

    // ----- layer 2 (+ fused layer-3 transform) -----
    gemm_dual_tf32_kernel<<<gemmGrd, 256>>>(feat, Wl2, Wr2, bl2, br2, xl, xr, nN, HID, HID);
    gat_fused_kernel<true><<<fusedGrid, 256>>>(xl, xr, att2, bias2, rowptr, eperm,
                                               nullptr, Wl3, bl3, Wr3, br3,
                                               xl3, xr3, nN);

    // ----- layer 3 -----
    l3_fused_kernel<<<fusedGrid, 256>>>(xl3, xr3, att3, bias3, rowptr, eperm,
                                        (float*)d_out, nN);
}